// round 1
// baseline (speedup 1.0000x reference)
#include <cuda_runtime.h>
#include <math.h>

#define NBATCH 8
#define NPTS   8192
#define NCAND  2048
#define PTS_PER_THREAD 2
#define NTHREADS 128
#define PTS_PER_BLOCK (NTHREADS * PTS_PER_THREAD)      // 256
#define BLOCKS_PER_BATCH (NPTS / PTS_PER_BLOCK)        // 32

#define BASE_ALPHA 0.05f
#define EPS_F      1e-6f

// Scratch (allocation-free rule: __device__ globals)
__device__ float g_mindist[NBATCH * NPTS];
__device__ int   g_bidx[NBATCH * NPTS];
__device__ int   g_batchmax[NBATCH];   // float bits (all dists >= 0, int order == float order)

__global__ void init_kernel() {
    if (threadIdx.x < NBATCH) g_batchmax[threadIdx.x] = 0;
}

__global__ __launch_bounds__(NTHREADS)
void nearest_kernel(const float* __restrict__ refined,
                    const float* __restrict__ partial) {
    __shared__ float4 sc[NCAND];                 // (cx, cy, cz, 0.5*|c|^2)  32 KB
    __shared__ float warpmax[NTHREADS / 32];

    const int b = blockIdx.y;
    const float* __restrict__ pp = partial + (size_t)b * NCAND * 3;

    // Cooperative load of this batch's candidates + precompute h = 0.5*|c|^2
    for (int j = threadIdx.x; j < NCAND; j += NTHREADS) {
        float x = pp[3 * j + 0];
        float y = pp[3 * j + 1];
        float z = pp[3 * j + 2];
        sc[j] = make_float4(x, y, z, 0.5f * (x * x + y * y + z * z));
    }
    __syncthreads();

    const int p0 = blockIdx.x * PTS_PER_BLOCK + threadIdx.x;
    const int p1 = p0 + NTHREADS;
    const float* __restrict__ rb = refined + (size_t)b * NPTS * 3;

    // Negate point coords so score = fma(ax,cx, fma(ay,cy, fma(az,cz,h)))
    const float ax0 = -rb[3 * p0 + 0], ay0 = -rb[3 * p0 + 1], az0 = -rb[3 * p0 + 2];
    const float ax1 = -rb[3 * p1 + 0], ay1 = -rb[3 * p1 + 1], az1 = -rb[3 * p1 + 2];

    float best0 = 3.0e38f, best1 = 3.0e38f;
    int   bi0 = 0, bi1 = 0;

    #pragma unroll 8
    for (int j = 0; j < NCAND; j++) {
        float4 c = sc[j];
        float s0 = fmaf(ax0, c.x, fmaf(ay0, c.y, fmaf(az0, c.z, c.w)));
        float s1 = fmaf(ax1, c.x, fmaf(ay1, c.y, fmaf(az1, c.z, c.w)));
        if (s0 < best0) { best0 = s0; bi0 = j; }   // strict < keeps first occurrence (jnp.argmin)
        if (s1 < best1) { best1 = s1; bi1 = j; }
    }

    const float p2_0 = ax0 * ax0 + ay0 * ay0 + az0 * az0;
    const float p2_1 = ax1 * ax1 + ay1 * ay1 + az1 * az1;
    const float d0 = sqrtf(fmaxf(p2_0 + 2.0f * best0, 0.0f));
    const float d1 = sqrtf(fmaxf(p2_1 + 2.0f * best1, 0.0f));

    g_mindist[b * NPTS + p0] = d0;  g_bidx[b * NPTS + p0] = bi0;
    g_mindist[b * NPTS + p1] = d1;  g_bidx[b * NPTS + p1] = bi1;

    // Block max -> single atomic per block
    float m = fmaxf(d0, d1);
    #pragma unroll
    for (int off = 16; off > 0; off >>= 1)
        m = fmaxf(m, __shfl_xor_sync(0xffffffffu, m, off));
    if ((threadIdx.x & 31) == 0) warpmax[threadIdx.x >> 5] = m;
    __syncthreads();
    if (threadIdx.x == 0) {
        float mm = warpmax[0];
        #pragma unroll
        for (int w = 1; w < NTHREADS / 32; w++) mm = fmaxf(mm, warpmax[w]);
        atomicMax(&g_batchmax[b], __float_as_int(mm));
    }
}

__global__ void update_kernel(const float* __restrict__ refined_in,
                              const float* __restrict__ partial,
                              float* __restrict__ out) {
    const int i = blockIdx.x * blockDim.x + threadIdx.x;   // global point index
    if (i >= NBATCH * NPTS) return;
    const int b = i / NPTS;

    const float maxd = __int_as_float(g_batchmax[b]);
    const float md   = g_mindist[i];
    const int   j    = g_bidx[i];

    const float dn    = md / (maxd + EPS_F);
    const float alpha = BASE_ALPHA * (2.0f - dn);

    const float* __restrict__ pc = partial + ((size_t)b * NCAND + j) * 3;
    const float rx = refined_in[3 * i + 0];
    const float ry = refined_in[3 * i + 1];
    const float rz = refined_in[3 * i + 2];

    out[3 * i + 0] = rx + alpha * (pc[0] - rx);
    out[3 * i + 1] = ry + alpha * (pc[1] - ry);
    out[3 * i + 2] = rz + alpha * (pc[2] - rz);
}

extern "C" void kernel_launch(void* const* d_in, const int* in_sizes, int n_in,
                              void* d_out, int out_size) {
    const float* pred    = (const float*)d_in[0];   // [8,8192,3]
    const float* partial = (const float*)d_in[1];   // [8,2048,3]
    float* out = (float*)d_out;                     // [8,8192,3]

    const dim3 ngrid(BLOCKS_PER_BATCH, NBATCH);
    const int  tot     = NBATCH * NPTS;
    const int  ublocks = (tot + 255) / 256;

    // Iteration 1: pred -> out
    init_kernel<<<1, 32>>>();
    nearest_kernel<<<ngrid, NTHREADS>>>(pred, partial);
    update_kernel<<<ublocks, 256>>>(pred, partial, out);

    // Iteration 2: out -> out
    init_kernel<<<1, 32>>>();
    nearest_kernel<<<ngrid, NTHREADS>>>(out, partial);
    update_kernel<<<ublocks, 256>>>(out, partial, out);
}

// round 2
// speedup vs baseline: 1.4315x; 1.4315x over previous
#include <cuda_runtime.h>
#include <math.h>

#define NBATCH 8
#define NPTS   8192
#define NCAND  2048
#define NPAIR  (NCAND / 2)          // 1024 candidate pairs
#define NTHREADS 256
#define PTS_PER_BLOCK 512           // 2 points per thread
#define NBLK (NPTS / PTS_PER_BLOCK) // 16 blocks per batch

#define BASE_ALPHA 0.05f
#define EPS_F      1e-6f

typedef unsigned long long ull;

// Scratch (allocation-free rule: __device__ globals). Set 1 = iter1, set 2 = iter2.
__device__ float g_md1[NBATCH * NPTS];
__device__ int   g_bi1[NBATCH * NPTS];
__device__ float g_bm1[NBATCH * NBLK];
__device__ float g_md2[NBATCH * NPTS];
__device__ int   g_bi2[NBATCH * NPTS];
__device__ float g_bm2[NBATCH * NBLK];

// ---- packed fp32x2 helpers (sm_100+; ptxas never emits FFMA2 from C++) ----
__device__ __forceinline__ ull ffma2(ull a, ull b, ull c) {
    ull d;
    asm("fma.rn.f32x2 %0, %1, %2, %3;" : "=l"(d) : "l"(a), "l"(b), "l"(c));
    return d;
}
__device__ __forceinline__ ull pack2(float lo, float hi) {
    ull r;
    asm("mov.b64 %0, {%1, %2};" : "=l"(r) : "f"(lo), "f"(hi));
    return r;
}
__device__ __forceinline__ void unpack2(ull v, float& lo, float& hi) {
    asm("mov.b64 {%0, %1}, %2;" : "=f"(lo), "=f"(hi) : "l"(v));
}

__device__ __forceinline__ float batch_max(const float* __restrict__ bm, int b) {
    float m = bm[b * NBLK];
#pragma unroll
    for (int k = 1; k < NBLK; k++) m = fmaxf(m, bm[b * NBLK + k]);
    return m;
}

// ITER==1: refined = pred, write set 1.
// ITER==2: refined = update(pred, set 1) computed in the prologue, write set 2.
template <int ITER>
__global__ __launch_bounds__(NTHREADS, 1)
void nearest_kernel(const float* __restrict__ pred,
                    const float* __restrict__ partial) {
    // pair g: sc[2g] = (x_even|x_odd , y_even|y_odd), sc[2g+1] = (z_e|z_o , h_e|h_o)
    // where h = 0.5*|c|^2.  32 KB total.
    __shared__ ulonglong2 sc[2 * NPAIR];
    __shared__ float s_warpmax[NTHREADS / 32];

    const int b = blockIdx.y;
    const float* __restrict__ pp = partial + (size_t)b * NCAND * 3;

    float* sf = reinterpret_cast<float*>(sc);
    for (int g = threadIdx.x; g < NPAIR; g += NTHREADS) {
        const float* q = pp + 6 * g;
        float x0 = q[0], y0 = q[1], z0 = q[2];
        float x1 = q[3], y1 = q[4], z1 = q[5];
        sf[8 * g + 0] = x0; sf[8 * g + 1] = x1;
        sf[8 * g + 2] = y0; sf[8 * g + 3] = y1;
        sf[8 * g + 4] = z0; sf[8 * g + 5] = z1;
        sf[8 * g + 6] = 0.5f * (x0 * x0 + y0 * y0 + z0 * z0);
        sf[8 * g + 7] = 0.5f * (x1 * x1 + y1 * y1 + z1 * z1);
    }
    __syncthreads();

    const int p0 = blockIdx.x * PTS_PER_BLOCK + threadIdx.x;  // batch-local point
    const int p1 = p0 + NTHREADS;
    const float* __restrict__ pb = pred + (size_t)b * NPTS * 3;

    // Load the two points (iter 2: apply iteration-1 update on the fly)
    float rx0 = pb[3 * p0], ry0 = pb[3 * p0 + 1], rz0 = pb[3 * p0 + 2];
    float rx1 = pb[3 * p1], ry1 = pb[3 * p1 + 1], rz1 = pb[3 * p1 + 2];
    if (ITER == 2) {
        const float bm = batch_max(g_bm1, b) + EPS_F;
        int gi = b * NPTS + p0;
        float a = BASE_ALPHA * (2.0f - g_md1[gi] / bm);
        const float* pc = pp + 3 * g_bi1[gi];
        rx0 += a * (pc[0] - rx0); ry0 += a * (pc[1] - ry0); rz0 += a * (pc[2] - rz0);
        gi = b * NPTS + p1;
        a = BASE_ALPHA * (2.0f - g_md1[gi] / bm);
        pc = pp + 3 * g_bi1[gi];
        rx1 += a * (pc[0] - rx1); ry1 += a * (pc[1] - ry1); rz1 += a * (pc[2] - rz1);
    }

    // score = -p.x*c.x - p.y*c.y - p.z*c.z + h  (argmin of 0.5*d^2 - 0.5*|p|^2)
    const ull ax0 = pack2(-rx0, -rx0), ay0 = pack2(-ry0, -ry0), az0 = pack2(-rz0, -rz0);
    const ull ax1 = pack2(-rx1, -rx1), ay1 = pack2(-ry1, -ry1), az1 = pack2(-rz1, -rz1);

    float best0 = 3.0e38f, best1 = 3.0e38f;
    int gi0 = 0, gi1 = 0;

#pragma unroll 8
    for (int g = 0; g < NPAIR; g++) {
        ulonglong2 A = sc[2 * g];       // (x2, y2)
        ulonglong2 B = sc[2 * g + 1];   // (z2, h2)
        ull t0 = ffma2(az0, B.x, B.y);
        t0 = ffma2(ay0, A.y, t0);
        t0 = ffma2(ax0, A.x, t0);
        ull t1 = ffma2(az1, B.x, B.y);
        t1 = ffma2(ay1, A.y, t1);
        t1 = ffma2(ax1, A.x, t1);
        float se0, so0, se1, so1;
        unpack2(t0, se0, so0);
        unpack2(t1, se1, so1);
        float gm0 = fminf(se0, so0);
        float gm1 = fminf(se1, so1);
        if (gm0 < best0) { best0 = gm0; gi0 = g; }  // strict <: first group wins ties
        if (gm1 < best1) { best1 = gm1; gi1 = g; }
    }

    // Resolve even/odd inside the winning pair; recompute even-lane score with an
    // identical FMA chain (bitwise equal to the f32x2 lane), <= keeps first index.
    int bi0, bi1;
    {
        const float* q = sf + 8 * gi0;
        float se = fmaf(-rx0, q[0], fmaf(-ry0, q[2], fmaf(-rz0, q[4], q[6])));
        bi0 = 2 * gi0 + ((se <= best0) ? 0 : 1);
        q = sf + 8 * gi1;
        se = fmaf(-rx1, q[0], fmaf(-ry1, q[2], fmaf(-rz1, q[4], q[6])));
        bi1 = 2 * gi1 + ((se <= best1) ? 0 : 1);
    }

    const float p20 = rx0 * rx0 + ry0 * ry0 + rz0 * rz0;
    const float p21 = rx1 * rx1 + ry1 * ry1 + rz1 * rz1;
    const float d0 = sqrtf(fmaxf(fmaf(2.0f, best0, p20), 0.0f));
    const float d1 = sqrtf(fmaxf(fmaf(2.0f, best1, p21), 0.0f));

    float* md_out = (ITER == 1) ? g_md1 : g_md2;
    int*   bi_out = (ITER == 1) ? g_bi1 : g_bi2;
    float* bm_out = (ITER == 1) ? g_bm1 : g_bm2;

    md_out[b * NPTS + p0] = d0; bi_out[b * NPTS + p0] = bi0;
    md_out[b * NPTS + p1] = d1; bi_out[b * NPTS + p1] = bi1;

    // Block max (no atomics, no init kernel: every slot written every launch)
    float m = fmaxf(d0, d1);
#pragma unroll
    for (int off = 16; off > 0; off >>= 1)
        m = fmaxf(m, __shfl_xor_sync(0xffffffffu, m, off));
    if ((threadIdx.x & 31) == 0) s_warpmax[threadIdx.x >> 5] = m;
    __syncthreads();
    if (threadIdx.x == 0) {
        float mm = s_warpmax[0];
#pragma unroll
        for (int w = 1; w < NTHREADS / 32; w++) mm = fmaxf(mm, s_warpmax[w]);
        bm_out[b * NBLK + blockIdx.x] = mm;
    }
}

// Replays update 1 (pred -> refined1) and update 2 (refined1 -> out).
__global__ void finalize_kernel(const float* __restrict__ pred,
                                const float* __restrict__ partial,
                                float* __restrict__ out) {
    const int i = blockIdx.x * blockDim.x + threadIdx.x;  // global point index
    if (i >= NBATCH * NPTS) return;
    const int b = i / NPTS;
    const float* __restrict__ pp = partial + (size_t)b * NCAND * 3;

    const float bm1 = batch_max(g_bm1, b) + EPS_F;
    const float bm2 = batch_max(g_bm2, b) + EPS_F;

    float rx = pred[3 * i], ry = pred[3 * i + 1], rz = pred[3 * i + 2];
    {
        float a = BASE_ALPHA * (2.0f - g_md1[i] / bm1);
        const float* pc = pp + 3 * g_bi1[i];
        rx += a * (pc[0] - rx); ry += a * (pc[1] - ry); rz += a * (pc[2] - rz);
    }
    {
        float a = BASE_ALPHA * (2.0f - g_md2[i] / bm2);
        const float* pc = pp + 3 * g_bi2[i];
        rx += a * (pc[0] - rx); ry += a * (pc[1] - ry); rz += a * (pc[2] - rz);
    }
    out[3 * i + 0] = rx;
    out[3 * i + 1] = ry;
    out[3 * i + 2] = rz;
}

extern "C" void kernel_launch(void* const* d_in, const int* in_sizes, int n_in,
                              void* d_out, int out_size) {
    const float* pred    = (const float*)d_in[0];   // [8,8192,3]
    const float* partial = (const float*)d_in[1];   // [8,2048,3]
    float* out = (float*)d_out;                     // [8,8192,3]

    const dim3 grid(NBLK, NBATCH);                  // 128 blocks, single wave
    const int tot = NBATCH * NPTS;

    nearest_kernel<1><<<grid, NTHREADS>>>(pred, partial);
    nearest_kernel<2><<<grid, NTHREADS>>>(pred, partial);
    finalize_kernel<<<(tot + 255) / 256, 256>>>(pred, partial, out);
}

// round 3
// speedup vs baseline: 1.4530x; 1.0150x over previous
#include <cuda_runtime.h>
#include <math.h>

#define NBATCH 8
#define NPTS   8192
#define NCAND  2048
#define NG4    (NCAND / 4)          // 512 groups of 4
#define NG8    (NCAND / 8)          // 256 groups of 8
#define NTHREADS 256
#define PTS_PER_BLOCK 512           // 2 points per thread
#define NBLK (NPTS / PTS_PER_BLOCK) // 16 blocks per batch

#define BASE_ALPHA 0.05f
#define EPS_F      1e-6f

typedef unsigned long long ull;

// Scratch (allocation-free rule: __device__ globals). Set 1 = iter1, set 2 = iter2.
__device__ float g_md1[NBATCH * NPTS];
__device__ int   g_bi1[NBATCH * NPTS];
__device__ float g_bm1[NBATCH * NBLK];
__device__ float g_md2[NBATCH * NPTS];
__device__ int   g_bi2[NBATCH * NPTS];
__device__ float g_bm2[NBATCH * NBLK];

// ---- packed fp32x2 helpers (sm_100+; ptxas never emits FFMA2 from C++) ----
__device__ __forceinline__ ull ffma2(ull a, ull b, ull c) {
    ull d;
    asm("fma.rn.f32x2 %0, %1, %2, %3;" : "=l"(d) : "l"(a), "l"(b), "l"(c));
    return d;
}
__device__ __forceinline__ ull pack2(float lo, float hi) {
    ull r;
    asm("mov.b64 %0, {%1, %2};" : "=l"(r) : "f"(lo), "f"(hi));
    return r;
}
__device__ __forceinline__ void unpack2(ull v, float& lo, float& hi) {
    asm("mov.b64 {%0, %1}, %2;" : "=f"(lo), "=f"(hi) : "l"(v));
}

__device__ __forceinline__ float batch_max(const float* __restrict__ bm, int b) {
    float m = bm[b * NBLK];
#pragma unroll
    for (int k = 1; k < NBLK; k++) m = fmaxf(m, bm[b * NBLK + k]);
    return m;
}

// min over 4 candidates stored as (xl,xh)(yl,yh)(zl,zh)(hl,hh) packed pairs.
// score = ax*x + (ay*y + (az*z + h)), ax = -px etc.  (argmin of 0.5*d^2 - 0.5*|p|^2)
__device__ __forceinline__ float min4(ull ax, ull ay, ull az,
                                      ulonglong2 X, ulonglong2 Y,
                                      ulonglong2 Z, ulonglong2 H) {
    ull tl = ffma2(az, Z.x, H.x);
    tl = ffma2(ay, Y.x, tl);
    tl = ffma2(ax, X.x, tl);
    ull th = ffma2(az, Z.y, H.y);
    th = ffma2(ay, Y.y, th);
    th = ffma2(ax, X.y, th);
    float s0, s1, s2, s3;
    unpack2(tl, s0, s1);
    unpack2(th, s2, s3);
    return fminf(fminf(s0, s1), fminf(s2, s3));
}

// Find first j in [0,8) of winning group-of-8 with score <= best.
// sf points at the group's smem floats: [x0..3 y0..3 z0..3 h0..3][x4..7 ...].
// Scalar FMA chain is bitwise-identical to the packed lanes -> exact match exists.
__device__ __forceinline__ int resolve8(const float* __restrict__ sf,
                                        float ax, float ay, float az, float best) {
    int r = 7;
#pragma unroll
    for (int j = 6; j >= 0; j--) {
        const int q = (j >> 2) * 16, l = j & 3;
        float s = fmaf(ax, sf[q + l],
                  fmaf(ay, sf[q + 4 + l],
                  fmaf(az, sf[q + 8 + l], sf[q + 12 + l])));
        if (s <= best) r = j;
    }
    return r;
}

// ITER==1: refined = pred, write set 1.
// ITER==2: refined = update(pred, set 1) computed in the prologue, write set 2.
template <int ITER>
__global__ __launch_bounds__(NTHREADS)
void nearest_kernel(const float* __restrict__ pred,
                    const float* __restrict__ partial) {
    // group-of-4 g: sG[4g+0]=(x0,x1,x2,x3), +1=y, +2=z, +3=h (h=0.5*|c|^2). 32KB.
    __shared__ float4 sG[4 * NG4];
    __shared__ float s_warpmax[NTHREADS / 32];

    const int b = blockIdx.y;
    const float* __restrict__ pp = partial + (size_t)b * NCAND * 3;
    const float4* __restrict__ pp4 = (const float4*)pp;

    // Cooperative transpose load: 3 float4 of AoS -> 4 float4 of SoA per group-of-4.
    for (int g = threadIdx.x; g < NG4; g += NTHREADS) {
        float4 A = pp4[3 * g + 0];   // x0 y0 z0 x1
        float4 B = pp4[3 * g + 1];   // y1 z1 x2 y2
        float4 C = pp4[3 * g + 2];   // z2 x3 y3 z3
        float4 X = make_float4(A.x, A.w, B.z, C.y);
        float4 Y = make_float4(A.y, B.x, B.w, C.z);
        float4 Z = make_float4(A.z, B.y, C.x, C.w);
        float4 H = make_float4(0.5f * (X.x * X.x + Y.x * Y.x + Z.x * Z.x),
                               0.5f * (X.y * X.y + Y.y * Y.y + Z.y * Z.y),
                               0.5f * (X.z * X.z + Y.z * Y.z + Z.z * Z.z),
                               0.5f * (X.w * X.w + Y.w * Y.w + Z.w * Z.w));
        sG[4 * g + 0] = X;
        sG[4 * g + 1] = Y;
        sG[4 * g + 2] = Z;
        sG[4 * g + 3] = H;
    }
    __syncthreads();

    const int p0 = blockIdx.x * PTS_PER_BLOCK + threadIdx.x;  // batch-local point
    const int p1 = p0 + NTHREADS;
    const float* __restrict__ pb = pred + (size_t)b * NPTS * 3;

    float rx0 = pb[3 * p0], ry0 = pb[3 * p0 + 1], rz0 = pb[3 * p0 + 2];
    float rx1 = pb[3 * p1], ry1 = pb[3 * p1 + 1], rz1 = pb[3 * p1 + 2];
    if (ITER == 2) {
        const float rbm = 1.0f / (batch_max(g_bm1, b) + EPS_F);
        int gi = b * NPTS + p0;
        float a = BASE_ALPHA * (2.0f - g_md1[gi] * rbm);
        const float* pc = pp + 3 * g_bi1[gi];
        rx0 += a * (pc[0] - rx0); ry0 += a * (pc[1] - ry0); rz0 += a * (pc[2] - rz0);
        gi = b * NPTS + p1;
        a = BASE_ALPHA * (2.0f - g_md1[gi] * rbm);
        pc = pp + 3 * g_bi1[gi];
        rx1 += a * (pc[0] - rx1); ry1 += a * (pc[1] - ry1); rz1 += a * (pc[2] - rz1);
    }

    const ull ax0 = pack2(-rx0, -rx0), ay0 = pack2(-ry0, -ry0), az0 = pack2(-rz0, -rz0);
    const ull ax1 = pack2(-rx1, -rx1), ay1 = pack2(-ry1, -ry1), az1 = pack2(-rz1, -rz1);

    float best0 = 3.0e38f, best1 = 3.0e38f;
    int gi0 = 0, gi1 = 0;

    const ulonglong2* __restrict__ su = reinterpret_cast<const ulonglong2*>(sG);

#pragma unroll 4
    for (int g = 0; g < NG8; g++) {
        // two groups-of-4, loaded straight into aligned 64-bit pairs (LDS.128)
        ulonglong2 Xa = su[8 * g + 0], Ya = su[8 * g + 1];
        ulonglong2 Za = su[8 * g + 2], Ha = su[8 * g + 3];
        ulonglong2 Xb = su[8 * g + 4], Yb = su[8 * g + 5];
        ulonglong2 Zb = su[8 * g + 6], Hb = su[8 * g + 7];

        float m0 = fminf(min4(ax0, ay0, az0, Xa, Ya, Za, Ha),
                         min4(ax0, ay0, az0, Xb, Yb, Zb, Hb));
        if (m0 < best0) { best0 = m0; gi0 = g; }   // strict <: first group wins ties

        float m1 = fminf(min4(ax1, ay1, az1, Xa, Ya, Za, Ha),
                         min4(ax1, ay1, az1, Xb, Yb, Zb, Hb));
        if (m1 < best1) { best1 = m1; gi1 = g; }
    }

    const float* sf = reinterpret_cast<const float*>(sG);
    const int bi0 = 8 * gi0 + resolve8(sf + 32 * gi0, -rx0, -ry0, -rz0, best0);
    const int bi1 = 8 * gi1 + resolve8(sf + 32 * gi1, -rx1, -ry1, -rz1, best1);

    const float p20 = rx0 * rx0 + ry0 * ry0 + rz0 * rz0;
    const float p21 = rx1 * rx1 + ry1 * ry1 + rz1 * rz1;
    const float d0 = sqrtf(fmaxf(fmaf(2.0f, best0, p20), 0.0f));
    const float d1 = sqrtf(fmaxf(fmaf(2.0f, best1, p21), 0.0f));

    float* md_out = (ITER == 1) ? g_md1 : g_md2;
    int*   bi_out = (ITER == 1) ? g_bi1 : g_bi2;
    float* bm_out = (ITER == 1) ? g_bm1 : g_bm2;

    md_out[b * NPTS + p0] = d0; bi_out[b * NPTS + p0] = bi0;
    md_out[b * NPTS + p1] = d1; bi_out[b * NPTS + p1] = bi1;

    // Block max (no atomics, no init kernel: every slot written every launch)
    float m = fmaxf(d0, d1);
#pragma unroll
    for (int off = 16; off > 0; off >>= 1)
        m = fmaxf(m, __shfl_xor_sync(0xffffffffu, m, off));
    if ((threadIdx.x & 31) == 0) s_warpmax[threadIdx.x >> 5] = m;
    __syncthreads();
    if (threadIdx.x == 0) {
        float mm = s_warpmax[0];
#pragma unroll
        for (int w = 1; w < NTHREADS / 32; w++) mm = fmaxf(mm, s_warpmax[w]);
        bm_out[b * NBLK + blockIdx.x] = mm;
    }
}

// Replays update 1 (pred -> refined1) and update 2 (refined1 -> out).
__global__ void finalize_kernel(const float* __restrict__ pred,
                                const float* __restrict__ partial,
                                float* __restrict__ out) {
    const int i = blockIdx.x * blockDim.x + threadIdx.x;  // global point index
    if (i >= NBATCH * NPTS) return;
    const int b = i / NPTS;
    const float* __restrict__ pp = partial + (size_t)b * NCAND * 3;

    const float rbm1 = 1.0f / (batch_max(g_bm1, b) + EPS_F);
    const float rbm2 = 1.0f / (batch_max(g_bm2, b) + EPS_F);

    float rx = pred[3 * i], ry = pred[3 * i + 1], rz = pred[3 * i + 2];
    {
        float a = BASE_ALPHA * (2.0f - g_md1[i] * rbm1);
        const float* pc = pp + 3 * g_bi1[i];
        rx += a * (pc[0] - rx); ry += a * (pc[1] - ry); rz += a * (pc[2] - rz);
    }
    {
        float a = BASE_ALPHA * (2.0f - g_md2[i] * rbm2);
        const float* pc = pp + 3 * g_bi2[i];
        rx += a * (pc[0] - rx); ry += a * (pc[1] - ry); rz += a * (pc[2] - rz);
    }
    out[3 * i + 0] = rx;
    out[3 * i + 1] = ry;
    out[3 * i + 2] = rz;
}

extern "C" void kernel_launch(void* const* d_in, const int* in_sizes, int n_in,
                              void* d_out, int out_size) {
    const float* pred    = (const float*)d_in[0];   // [8,8192,3]
    const float* partial = (const float*)d_in[1];   // [8,2048,3]
    float* out = (float*)d_out;                     // [8,8192,3]

    const dim3 grid(NBLK, NBATCH);                  // 128 blocks, single wave
    const int tot = NBATCH * NPTS;

    nearest_kernel<1><<<grid, NTHREADS>>>(pred, partial);
    nearest_kernel<2><<<grid, NTHREADS>>>(pred, partial);
    finalize_kernel<<<(tot + 255) / 256, 256>>>(pred, partial, out);
}